// round 2
// baseline (speedup 1.0000x reference)
#include <cuda_runtime.h>

// Problem constants
#define B_    10      // 2 * IMG_COUNT sequences
#define T_    576     // tokens per sequence
#define C_    1280    // channels
#define H_    20      // heads
#define HD_   64      // head dim
#define P_    5       // plates (IMG_COUNT)
#define NSEL_ 288     // selected tokens per plate
#define TK_   1728    // kv length = 4*288 + 576
#define BQ_   64      // q tile
#define BKV_  32      // kv chunk
#define NCH_  (TK_/BKV_)   // 54 chunks

// Scratch (device globals: allocation APIs are forbidden)
__device__ float g_Q [B_*T_*C_];
__device__ float g_K [B_*T_*C_];
__device__ float g_V [B_*T_*C_];
__device__ float g_AO[B_*T_*C_];
__device__ int   g_kvrows[B_*TK_];

// ---------------------------------------------------------------------------
// Build per-(s,i) KV row index table. kv row m maps to a global row of the
// pre-projected K/V tensors (10*576 rows). Handles int64-vs-int32 `indices`
// at runtime (jax may silently demote int64 -> int32).
// ---------------------------------------------------------------------------
__global__ void build_kv_kernel(const void* __restrict__ idx_raw) {
    const int*       i32 = (const int*)idx_raw;
    const long long* i64 = (const long long*)idx_raw;
    // dtype detection: int64 values < 576 -> every high 32-bit word is 0.
    bool is64 = true;
    #pragma unroll 8
    for (int k = 0; k < 64; k++) {
        if (i32[2*k + 1] != 0) { is64 = false; break; }
    }
    const int b = blockIdx.x;       // 0..9
    const int s = b / P_, i = b % P_;
    for (int m = threadIdx.x; m < TK_; m += blockDim.x) {
        int row;
        if (m < (P_-1)*NSEL_) {
            int prel = m / NSEL_;
            int p    = prel + (prel >= i ? 1 : 0);
            int j    = m - prel * NSEL_;
            int tok  = is64 ? (int)i64[p*NSEL_ + j] : i32[p*NSEL_ + j];
            row = (s*P_ + p) * T_ + tok;
        } else {
            row = (s*P_ + i) * T_ + (m - (P_-1)*NSEL_);
        }
        g_kvrows[b*TK_ + m] = row;
    }
}

// ---------------------------------------------------------------------------
// Y[m][n] = sum_k A[m][k] * Bw[n][k]  (+ bias[n])      -- i.e. Y = A @ Bw^T
// 64x64 tile, BK=16, 256 threads, 4x4 per thread, transposed smem tiles,
// single-stage register prefetch of the next gmem tile.
// ---------------------------------------------------------------------------
__global__ __launch_bounds__(256) void gemm_nt_kernel(
    const float* __restrict__ A, const float* __restrict__ Bw,
    const float* __restrict__ bias, float* __restrict__ Yo,
    int M, int N, int K)
{
    __shared__ float At[16][68];   // At[k][row]
    __shared__ float Bt[16][68];   // Bt[k][col]

    const int tid = threadIdx.x;
    const int tx  = tid & 15, ty = tid >> 4;
    const int m0  = blockIdx.y * 64, n0 = blockIdx.x * 64;
    const int lr  = tid >> 2;            // 0..63 (tile row for loading)
    const int lk  = (tid & 3) << 2;      // 0,4,8,12 (k offset for loading)

    const float* Ap = A  + (size_t)(m0 + lr) * K + lk;
    const float* Bp = Bw + (size_t)(n0 + lr) * K + lk;

    float acc[4][4];
    #pragma unroll
    for (int u = 0; u < 4; u++)
        #pragma unroll
        for (int v = 0; v < 4; v++) acc[u][v] = 0.f;

    float4 av = *(const float4*)Ap;
    float4 bv = *(const float4*)Bp;

    for (int k0 = 16; k0 <= K; k0 += 16) {
        At[lk+0][lr] = av.x; At[lk+1][lr] = av.y; At[lk+2][lr] = av.z; At[lk+3][lr] = av.w;
        Bt[lk+0][lr] = bv.x; Bt[lk+1][lr] = bv.y; Bt[lk+2][lr] = bv.z; Bt[lk+3][lr] = bv.w;
        __syncthreads();
        if (k0 < K) {           // prefetch next tile while computing this one
            av = *(const float4*)(Ap + k0);
            bv = *(const float4*)(Bp + k0);
        }
        #pragma unroll
        for (int kk = 0; kk < 16; kk++) {
            float4 a = *(const float4*)&At[kk][ty*4];
            float4 b = *(const float4*)&Bt[kk][tx*4];
            acc[0][0] += a.x*b.x; acc[0][1] += a.x*b.y; acc[0][2] += a.x*b.z; acc[0][3] += a.x*b.w;
            acc[1][0] += a.y*b.x; acc[1][1] += a.y*b.y; acc[1][2] += a.y*b.z; acc[1][3] += a.y*b.w;
            acc[2][0] += a.z*b.x; acc[2][1] += a.z*b.y; acc[2][2] += a.z*b.z; acc[2][3] += a.z*b.w;
            acc[3][0] += a.w*b.x; acc[3][1] += a.w*b.y; acc[3][2] += a.w*b.z; acc[3][3] += a.w*b.w;
        }
        __syncthreads();
    }

    const int mr = m0 + ty*4, nc = n0 + tx*4;
    float4 bb = make_float4(0.f, 0.f, 0.f, 0.f);
    if (bias) bb = *(const float4*)(bias + nc);
    #pragma unroll
    for (int u = 0; u < 4; u++) {
        float4 r4;
        r4.x = acc[u][0] + bb.x; r4.y = acc[u][1] + bb.y;
        r4.z = acc[u][2] + bb.z; r4.w = acc[u][3] + bb.w;
        *(float4*)(Yo + (size_t)(mr + u) * N + nc) = r4;
    }
}

// ---------------------------------------------------------------------------
// Flash-style attention. One block = (q-tile of 64 rows) x (one head) x (one
// of 10 (s,i) sequences). KV gathered through g_kvrows from the
// once-projected K/V (stays L2-resident). Online softmax; O accumulated in a
// 4x4/thread register tile (GEMM layout), per-row scale/inv exchanged via smem.
// ---------------------------------------------------------------------------
__global__ __launch_bounds__(256) void attn_kernel() {
    __shared__ float Qs[HD_][BQ_ + 4];     // Qs[d][r], pre-scaled by 1/8
    __shared__ float Ks[HD_][BKV_ + 2];    // Ks[d][j]
    __shared__ float Vs[BKV_][HD_ + 4];    // Vs[j][d]
    __shared__ float Ss[BQ_][BKV_ + 1];    // scores then probs
    __shared__ float rowscale[BQ_];
    __shared__ float rowinv[BQ_];

    const int qt = blockIdx.x, h = blockIdx.y, b = blockIdx.z;
    const int tid = threadIdx.x;
    const int tx  = tid & 15, ty = tid >> 4;   // S/PV gemm layout
    const int rr  = tid >> 2, qd = tid & 3;    // softmax quad layout
    const int hoff = h * HD_;
    const int* rows = g_kvrows + b * TK_;

    // Load+scale Q tile (transposed)
    for (int idx = tid; idx < BQ_*HD_; idx += 256) {
        int r = idx >> 6, d = idx & 63;
        Qs[d][r] = g_Q[(size_t)(b*T_ + qt*BQ_ + r) * C_ + hoff + d] * 0.125f;
    }

    float acc[4][4];
    #pragma unroll
    for (int u = 0; u < 4; u++)
        #pragma unroll
        for (int v = 0; v < 4; v++) acc[u][v] = 0.f;
    float m = -1e30f, l = 0.f;

    for (int ch = 0; ch < NCH_; ch++) {
        // Gather K (transposed) and V chunk
        for (int idx = tid; idx < BKV_*HD_; idx += 256) {
            int j = idx >> 6, d = idx & 63;
            int src = rows[ch*BKV_ + j];
            size_t g = (size_t)src * C_ + hoff + d;
            Ks[d][j] = g_K[g];
            Vs[j][d] = g_V[g];
        }
        __syncthreads();

        // S tile (64x32): thread computes rows ty*4..+4, cols tx*2..+2
        float sa[4][2];
        #pragma unroll
        for (int u = 0; u < 4; u++) { sa[u][0] = 0.f; sa[u][1] = 0.f; }
        #pragma unroll 16
        for (int d = 0; d < HD_; d++) {
            float4 a = *(const float4*)&Qs[d][ty*4];
            float b0 = Ks[d][tx*2 + 0];
            float b1 = Ks[d][tx*2 + 1];
            sa[0][0] += a.x*b0; sa[0][1] += a.x*b1;
            sa[1][0] += a.y*b0; sa[1][1] += a.y*b1;
            sa[2][0] += a.z*b0; sa[2][1] += a.z*b1;
            sa[3][0] += a.w*b0; sa[3][1] += a.w*b1;
        }
        #pragma unroll
        for (int u = 0; u < 4; u++) {
            Ss[ty*4 + u][tx*2 + 0] = sa[u][0];
            Ss[ty*4 + u][tx*2 + 1] = sa[u][1];
        }
        __syncthreads();

        // Online softmax: quad (4 lanes) per row, 8 scores each
        float sv[8];
        #pragma unroll
        for (int w = 0; w < 8; w++) sv[w] = Ss[rr][qd*8 + w];
        float cm = sv[0];
        #pragma unroll
        for (int w = 1; w < 8; w++) cm = fmaxf(cm, sv[w]);
        cm = fmaxf(cm, __shfl_xor_sync(0xffffffffu, cm, 1));
        cm = fmaxf(cm, __shfl_xor_sync(0xffffffffu, cm, 2));
        float mn   = fmaxf(m, cm);
        float corr = __expf(m - mn);
        float ps   = 0.f;
        #pragma unroll
        for (int w = 0; w < 8; w++) {
            float p = __expf(sv[w] - mn);
            ps += p;
            Ss[rr][qd*8 + w] = p;
        }
        ps += __shfl_xor_sync(0xffffffffu, ps, 1);
        ps += __shfl_xor_sync(0xffffffffu, ps, 2);
        l = l * corr + ps;
        m = mn;
        if (qd == 0) rowscale[rr] = corr;
        __syncthreads();

        // Rescale O and accumulate P @ V (64x64 += 64x32 @ 32x64)
        float s0 = rowscale[ty*4 + 0], s1 = rowscale[ty*4 + 1];
        float s2 = rowscale[ty*4 + 2], s3 = rowscale[ty*4 + 3];
        #pragma unroll
        for (int v = 0; v < 4; v++) {
            acc[0][v] *= s0; acc[1][v] *= s1; acc[2][v] *= s2; acc[3][v] *= s3;
        }
        #pragma unroll 8
        for (int j = 0; j < BKV_; j++) {
            float p0 = Ss[ty*4 + 0][j];
            float p1 = Ss[ty*4 + 1][j];
            float p2 = Ss[ty*4 + 2][j];
            float p3 = Ss[ty*4 + 3][j];
            float4 vv = *(const float4*)&Vs[j][tx*4];
            acc[0][0] += p0*vv.x; acc[0][1] += p0*vv.y; acc[0][2] += p0*vv.z; acc[0][3] += p0*vv.w;
            acc[1][0] += p1*vv.x; acc[1][1] += p1*vv.y; acc[1][2] += p1*vv.z; acc[1][3] += p1*vv.w;
            acc[2][0] += p2*vv.x; acc[2][1] += p2*vv.y; acc[2][2] += p2*vv.z; acc[2][3] += p2*vv.w;
            acc[3][0] += p3*vv.x; acc[3][1] += p3*vv.y; acc[3][2] += p3*vv.z; acc[3][3] += p3*vv.w;
        }
        __syncthreads();
    }

    if (qd == 0) rowinv[rr] = 1.f / l;
    __syncthreads();
    #pragma unroll
    for (int u = 0; u < 4; u++) {
        float inv = rowinv[ty*4 + u];
        float4 r4;
        r4.x = acc[u][0]*inv; r4.y = acc[u][1]*inv;
        r4.z = acc[u][2]*inv; r4.w = acc[u][3]*inv;
        *(float4*)&g_AO[(size_t)(b*T_ + qt*BQ_ + ty*4 + u) * C_ + hoff + tx*4] = r4;
    }
}

// ---------------------------------------------------------------------------
extern "C" void kernel_launch(void* const* d_in, const int* in_sizes, int n_in,
                              void* d_out, int out_size) {
    const float* hs  = (const float*)d_in[0];
    const float* Wq  = (const float*)d_in[1];
    const float* Wk  = (const float*)d_in[2];
    const float* Wv  = (const float*)d_in[3];
    const float* Wo  = (const float*)d_in[4];
    const float* bo  = (const float*)d_in[5];
    const void*  idx = d_in[6];
    float* out = (float*)d_out;

    float *Qp, *Kp, *Vp, *Ap;
    cudaGetSymbolAddress((void**)&Qp, g_Q);
    cudaGetSymbolAddress((void**)&Kp, g_K);
    cudaGetSymbolAddress((void**)&Vp, g_V);
    cudaGetSymbolAddress((void**)&Ap, g_AO);

    build_kv_kernel<<<B_, 256>>>(idx);

    dim3 gg(C_/64, (B_*T_)/64);   // (20, 90)
    gemm_nt_kernel<<<gg, 256>>>(hs, Wq, nullptr, Qp, B_*T_, C_, C_);
    gemm_nt_kernel<<<gg, 256>>>(hs, Wk, nullptr, Kp, B_*T_, C_, C_);
    gemm_nt_kernel<<<gg, 256>>>(hs, Wv, nullptr, Vp, B_*T_, C_, C_);

    dim3 ga(T_/BQ_, H_, B_);      // (9, 20, 10)
    attn_kernel<<<ga, 256>>>();

    gemm_nt_kernel<<<gg, 256>>>(Ap, Wo, bo, out, B_*T_, C_, C_);
}

// round 5
// speedup vs baseline: 1.3317x; 1.3317x over previous
#include <cuda_runtime.h>
#include <cstdint>

// Problem constants
#define B_    10      // 2 * IMG_COUNT sequences
#define T_    576     // tokens per sequence
#define C_    1280    // channels
#define H_    20      // heads
#define HD_   64      // head dim
#define P_    5       // plates
#define NSEL_ 288     // selected tokens per plate
#define TK_   1728    // kv length
#define BQ_   64
#define BKV_  32
#define NCH_  (TK_/BKV_)

// Scratch (device globals: allocation APIs are forbidden)
__device__ __align__(256) float g_Q [B_*T_*C_];
__device__ __align__(256) float g_K [B_*T_*C_];
__device__ __align__(256) float g_V [B_*T_*C_];
__device__ __align__(256) float g_AO[B_*T_*C_];
__device__ int g_kvrows[B_*TK_];

// ---------------------------------------------------------------------------
// Portable tf32 tensor-core MMA (sm_80+). HW reads operand bits[31:13] (RZ
// truncation to tf32) -- exploited for the big/small split below.
// ---------------------------------------------------------------------------
__device__ __forceinline__ void mma_tf32(float* c, const uint32_t* a, const uint32_t* b) {
    asm volatile(
        "mma.sync.aligned.m16n8k8.row.col.f32.tf32.tf32.f32 "
        "{%0,%1,%2,%3}, {%4,%5,%6,%7}, {%8,%9}, {%0,%1,%2,%3};"
        : "+f"(c[0]), "+f"(c[1]), "+f"(c[2]), "+f"(c[3])
        : "r"(a[0]), "r"(a[1]), "r"(a[2]), "r"(a[3]), "r"(b[0]), "r"(b[1]));
}

// small residual: x - tf32_truncate(x)   (exact in fp32)
__device__ __forceinline__ uint32_t tf32_small(float v) {
    uint32_t big = __float_as_uint(v) & 0xFFFFE000u;
    return __float_as_uint(v - __uint_as_float(big));
}

// ---------------------------------------------------------------------------
// Build per-(s,i) KV row index table (int64/int32 runtime detect).
// ---------------------------------------------------------------------------
__global__ void build_kv_kernel(const void* __restrict__ idx_raw) {
    const int*       i32 = (const int*)idx_raw;
    const long long* i64 = (const long long*)idx_raw;
    bool is64 = true;
    #pragma unroll 8
    for (int k = 0; k < 64; k++) {
        if (i32[2*k + 1] != 0) { is64 = false; break; }
    }
    const int b = blockIdx.x;
    const int s = b / P_, i = b % P_;
    for (int m = threadIdx.x; m < TK_; m += blockDim.x) {
        int row;
        if (m < (P_-1)*NSEL_) {
            int prel = m / NSEL_;
            int p    = prel + (prel >= i ? 1 : 0);
            int j    = m - prel * NSEL_;
            int tok  = is64 ? (int)i64[p*NSEL_ + j] : i32[p*NSEL_ + j];
            row = (s*P_ + p) * T_ + tok;
        } else {
            row = (s*P_ + i) * T_ + (m - (P_-1)*NSEL_);
        }
        g_kvrows[b*TK_ + m] = row;
    }
}

// ---------------------------------------------------------------------------
// 3xTF32 split-precision GEMM:  Y[m][n] = sum_k A[m][k]*Bw[n][k] (+bias[n])
// Each product ab = (ab_big+ab_small)(bb_big+bb_small); we accumulate
// bb*bb + bb*bs + as*bb on the tensor pipe (ss term ~2^-20, dropped).
// 128x128 CTA tile, 8 warps (64x32 each = 4x4 m16n8k8), BK=32,
// padded smem [128][36], reg-prefetched gmem loads.
// ---------------------------------------------------------------------------
__global__ __launch_bounds__(256) void gemm_mma_kernel(
    const float* __restrict__ A, const float* __restrict__ Bw,
    const float* __restrict__ bias, float* __restrict__ Y,
    int M, int N, int K)
{
    __shared__ float As[128][36];
    __shared__ float Bs[128][36];

    const int tid = threadIdx.x, wid = tid >> 5, lane = tid & 31;
    const int g = lane >> 2, tig = lane & 3;
    const int wm = (wid & 1) * 64, wn = (wid >> 1) * 32;
    const int m0 = blockIdx.y * 128, n0 = blockIdx.x * 128;
    const int NST = K >> 5;

    const int r = tid >> 1, half = tid & 1;
    const float* pA = A  + (size_t)(m0 + r) * K + half * 16;
    const float* pB = Bw + (size_t)(n0 + r) * K + half * 16;

    float acc[16][4];
    #pragma unroll
    for (int t = 0; t < 16; t++)
        #pragma unroll
        for (int v = 0; v < 4; v++) acc[t][v] = 0.f;

    float4 ra[4], rb[4];
    #pragma unroll
    for (int j = 0; j < 4; j++) {
        ra[j] = *(const float4*)(pA + j*4);
        rb[j] = *(const float4*)(pB + j*4);
    }

    for (int s = 0; s < NST; s++) {
        #pragma unroll
        for (int j = 0; j < 4; j++) {
            *(float4*)&As[r][half*16 + j*4] = ra[j];
            *(float4*)&Bs[r][half*16 + j*4] = rb[j];
        }
        __syncthreads();

        if (s + 1 < NST) {
            const float* a2 = pA + (s+1) * 32;
            const float* b2 = pB + (s+1) * 32;
            #pragma unroll
            for (int j = 0; j < 4; j++) {
                ra[j] = *(const float4*)(a2 + j*4);
                rb[j] = *(const float4*)(b2 + j*4);
            }
        }

        #pragma unroll
        for (int kb = 0; kb < 32; kb += 8) {
            uint32_t af[4][4], asm_[4][4], bf[4][2], bsm[4][2];
            #pragma unroll
            for (int mt = 0; mt < 4; mt++) {
                const int rb0 = wm + mt*16 + g;
                float v0 = As[rb0    ][kb + tig    ];
                float v1 = As[rb0 + 8][kb + tig    ];
                float v2 = As[rb0    ][kb + tig + 4];
                float v3 = As[rb0 + 8][kb + tig + 4];
                af[mt][0] = __float_as_uint(v0); asm_[mt][0] = tf32_small(v0);
                af[mt][1] = __float_as_uint(v1); asm_[mt][1] = tf32_small(v1);
                af[mt][2] = __float_as_uint(v2); asm_[mt][2] = tf32_small(v2);
                af[mt][3] = __float_as_uint(v3); asm_[mt][3] = tf32_small(v3);
            }
            #pragma unroll
            for (int nt = 0; nt < 4; nt++) {
                const int nb0 = wn + nt*8 + g;
                float w0 = Bs[nb0][kb + tig    ];
                float w1 = Bs[nb0][kb + tig + 4];
                bf[nt][0] = __float_as_uint(w0); bsm[nt][0] = tf32_small(w0);
                bf[nt][1] = __float_as_uint(w1); bsm[nt][1] = tf32_small(w1);
            }
            #pragma unroll
            for (int mt = 0; mt < 4; mt++)
                #pragma unroll
                for (int nt = 0; nt < 4; nt++) {
                    float* c = acc[mt*4 + nt];
                    mma_tf32(c, af[mt],   bf[nt]);    // big  * big
                    mma_tf32(c, af[mt],   bsm[nt]);   // big  * small
                    mma_tf32(c, asm_[mt], bf[nt]);    // small* big
                }
        }
        __syncthreads();
    }

    // Epilogue: registers -> gmem (+bias)
    #pragma unroll
    for (int mt = 0; mt < 4; mt++) {
        #pragma unroll
        for (int nt = 0; nt < 4; nt++) {
            const float* c = acc[mt*4 + nt];
            const int row = m0 + wm + mt*16 + g;
            const int col = n0 + wn + nt*8 + 2*tig;
            float b0c = 0.f, b1c = 0.f;
            if (bias) { b0c = bias[col]; b1c = bias[col + 1]; }
            float2 v0 = make_float2(c[0] + b0c, c[1] + b1c);
            float2 v1 = make_float2(c[2] + b0c, c[3] + b1c);
            *(float2*)(Y + (size_t)row       * N + col) = v0;
            *(float2*)(Y + (size_t)(row + 8) * N + col) = v1;
        }
    }
}

// ---------------------------------------------------------------------------
// Flash-style fp32 attention (unchanged from passing R1 version).
// ---------------------------------------------------------------------------
__global__ __launch_bounds__(256) void attn_kernel() {
    __shared__ float Qs[HD_][BQ_ + 4];
    __shared__ float Ks[HD_][BKV_ + 2];
    __shared__ float Vs[BKV_][HD_ + 4];
    __shared__ float Ss[BQ_][BKV_ + 1];
    __shared__ float rowscale[BQ_];
    __shared__ float rowinv[BQ_];

    const int qt = blockIdx.x, h = blockIdx.y, b = blockIdx.z;
    const int tid = threadIdx.x;
    const int tx  = tid & 15, ty = tid >> 4;
    const int rr  = tid >> 2, qd = tid & 3;
    const int hoff = h * HD_;
    const int* rows = g_kvrows + b * TK_;

    for (int idx = tid; idx < BQ_*HD_; idx += 256) {
        int r = idx >> 6, d = idx & 63;
        Qs[d][r] = g_Q[(size_t)(b*T_ + qt*BQ_ + r) * C_ + hoff + d] * 0.125f;
    }

    float acc[4][4];
    #pragma unroll
    for (int u = 0; u < 4; u++)
        #pragma unroll
        for (int v = 0; v < 4; v++) acc[u][v] = 0.f;
    float m = -1e30f, l = 0.f;

    for (int ch = 0; ch < NCH_; ch++) {
        for (int idx = tid; idx < BKV_*HD_; idx += 256) {
            int j = idx >> 6, d = idx & 63;
            int src = rows[ch*BKV_ + j];
            size_t gg = (size_t)src * C_ + hoff + d;
            Ks[d][j] = g_K[gg];
            Vs[j][d] = g_V[gg];
        }
        __syncthreads();

        float sa[4][2];
        #pragma unroll
        for (int u = 0; u < 4; u++) { sa[u][0] = 0.f; sa[u][1] = 0.f; }
        #pragma unroll 16
        for (int d = 0; d < HD_; d++) {
            float4 a = *(const float4*)&Qs[d][ty*4];
            float b0 = Ks[d][tx*2 + 0];
            float b1 = Ks[d][tx*2 + 1];
            sa[0][0] += a.x*b0; sa[0][1] += a.x*b1;
            sa[1][0] += a.y*b0; sa[1][1] += a.y*b1;
            sa[2][0] += a.z*b0; sa[2][1] += a.z*b1;
            sa[3][0] += a.w*b0; sa[3][1] += a.w*b1;
        }
        #pragma unroll
        for (int u = 0; u < 4; u++) {
            Ss[ty*4 + u][tx*2 + 0] = sa[u][0];
            Ss[ty*4 + u][tx*2 + 1] = sa[u][1];
        }
        __syncthreads();

        float sv[8];
        #pragma unroll
        for (int w = 0; w < 8; w++) sv[w] = Ss[rr][qd*8 + w];
        float cm = sv[0];
        #pragma unroll
        for (int w = 1; w < 8; w++) cm = fmaxf(cm, sv[w]);
        cm = fmaxf(cm, __shfl_xor_sync(0xffffffffu, cm, 1));
        cm = fmaxf(cm, __shfl_xor_sync(0xffffffffu, cm, 2));
        float mn   = fmaxf(m, cm);
        float corr = __expf(m - mn);
        float ps   = 0.f;
        #pragma unroll
        for (int w = 0; w < 8; w++) {
            float p = __expf(sv[w] - mn);
            ps += p;
            Ss[rr][qd*8 + w] = p;
        }
        ps += __shfl_xor_sync(0xffffffffu, ps, 1);
        ps += __shfl_xor_sync(0xffffffffu, ps, 2);
        l = l * corr + ps;
        m = mn;
        if (qd == 0) rowscale[rr] = corr;
        __syncthreads();

        float s0 = rowscale[ty*4 + 0], s1 = rowscale[ty*4 + 1];
        float s2 = rowscale[ty*4 + 2], s3 = rowscale[ty*4 + 3];
        #pragma unroll
        for (int v = 0; v < 4; v++) {
            acc[0][v] *= s0; acc[1][v] *= s1; acc[2][v] *= s2; acc[3][v] *= s3;
        }
        #pragma unroll 8
        for (int j = 0; j < BKV_; j++) {
            float p0 = Ss[ty*4 + 0][j];
            float p1 = Ss[ty*4 + 1][j];
            float p2 = Ss[ty*4 + 2][j];
            float p3 = Ss[ty*4 + 3][j];
            float4 vv = *(const float4*)&Vs[j][tx*4];
            acc[0][0] += p0*vv.x; acc[0][1] += p0*vv.y; acc[0][2] += p0*vv.z; acc[0][3] += p0*vv.w;
            acc[1][0] += p1*vv.x; acc[1][1] += p1*vv.y; acc[1][2] += p1*vv.z; acc[1][3] += p1*vv.w;
            acc[2][0] += p2*vv.x; acc[2][1] += p2*vv.y; acc[2][2] += p2*vv.z; acc[2][3] += p2*vv.w;
            acc[3][0] += p3*vv.x; acc[3][1] += p3*vv.y; acc[3][2] += p3*vv.z; acc[3][3] += p3*vv.w;
        }
        __syncthreads();
    }

    if (qd == 0) rowinv[rr] = 1.f / l;
    __syncthreads();
    #pragma unroll
    for (int u = 0; u < 4; u++) {
        float inv = rowinv[ty*4 + u];
        float4 r4;
        r4.x = acc[u][0]*inv; r4.y = acc[u][1]*inv;
        r4.z = acc[u][2]*inv; r4.w = acc[u][3]*inv;
        *(float4*)&g_AO[(size_t)(b*T_ + qt*BQ_ + ty*4 + u) * C_ + hoff + tx*4] = r4;
    }
}

// ---------------------------------------------------------------------------
extern "C" void kernel_launch(void* const* d_in, const int* in_sizes, int n_in,
                              void* d_out, int out_size) {
    const float* hs  = (const float*)d_in[0];
    const float* Wq  = (const float*)d_in[1];
    const float* Wk  = (const float*)d_in[2];
    const float* Wv  = (const float*)d_in[3];
    const float* Wo  = (const float*)d_in[4];
    const float* bo  = (const float*)d_in[5];
    const void*  idx = d_in[6];
    float* out = (float*)d_out;

    float *Qp, *Kp, *Vp, *Ap;
    cudaGetSymbolAddress((void**)&Qp, g_Q);
    cudaGetSymbolAddress((void**)&Kp, g_K);
    cudaGetSymbolAddress((void**)&Vp, g_V);
    cudaGetSymbolAddress((void**)&Ap, g_AO);

    build_kv_kernel<<<B_, 256>>>(idx);

    dim3 gg(C_/128, (B_*T_)/128);       // (10, 45)
    gemm_mma_kernel<<<gg, 256>>>(hs, Wq, nullptr, Qp, B_*T_, C_, C_);
    gemm_mma_kernel<<<gg, 256>>>(hs, Wk, nullptr, Kp, B_*T_, C_, C_);
    gemm_mma_kernel<<<gg, 256>>>(hs, Wv, nullptr, Vp, B_*T_, C_, C_);

    dim3 ga(T_/BQ_, H_, B_);            // (9, 20, 10)
    attn_kernel<<<ga, 256>>>();

    gemm_mma_kernel<<<gg, 256>>>(Ap, Wo, bo, out, B_*T_, C_, C_);
}

// round 7
// speedup vs baseline: 1.5541x; 1.1670x over previous
#include <cuda_runtime.h>
#include <cstdint>

// Problem constants
#define B_    10      // 2 * IMG_COUNT sequences
#define T_    576     // tokens per sequence
#define C_    1280    // channels
#define H_    20      // heads
#define HD_   64      // head dim
#define P_    5       // plates
#define NSEL_ 288     // selected tokens per plate
#define TK_   1728    // kv length
#define BQ_   64
#define BKV_  32
#define NCH_  (TK_/BKV_)

// Scratch (device globals: allocation APIs are forbidden)
__device__ __align__(256) float g_Q [B_*T_*C_];
__device__ __align__(256) float g_K [B_*T_*C_];
__device__ __align__(256) float g_V [B_*T_*C_];
__device__ __align__(256) float g_AO[B_*T_*C_];
__device__ int g_kvrows[B_*TK_];

// ---------------------------------------------------------------------------
// Portable tf32 tensor-core MMA (sm_80+). HW reads operand bits[31:13] (RZ
// truncation) -- exploited for the big/small 3xTF32 split.
// ---------------------------------------------------------------------------
__device__ __forceinline__ void mma_tf32(float* c, const uint32_t* a, const uint32_t* b) {
    asm volatile(
        "mma.sync.aligned.m16n8k8.row.col.f32.tf32.tf32.f32 "
        "{%0,%1,%2,%3}, {%4,%5,%6,%7}, {%8,%9}, {%0,%1,%2,%3};"
        : "+f"(c[0]), "+f"(c[1]), "+f"(c[2]), "+f"(c[3])
        : "r"(a[0]), "r"(a[1]), "r"(a[2]), "r"(a[3]), "r"(b[0]), "r"(b[1]));
}

__device__ __forceinline__ uint32_t tf32_small(float v) {
    uint32_t big = __float_as_uint(v) & 0xFFFFE000u;
    return __float_as_uint(v - __uint_as_float(big));
}

// ---------------------------------------------------------------------------
// Build per-(s,i) KV row index table (int64/int32 runtime detect).
// ---------------------------------------------------------------------------
__global__ void build_kv_kernel(const void* __restrict__ idx_raw) {
    const int*       i32 = (const int*)idx_raw;
    const long long* i64 = (const long long*)idx_raw;
    bool is64 = true;
    #pragma unroll 8
    for (int k = 0; k < 64; k++) {
        if (i32[2*k + 1] != 0) { is64 = false; break; }
    }
    const int b = blockIdx.x;
    const int s = b / P_, i = b % P_;
    for (int m = threadIdx.x; m < TK_; m += blockDim.x) {
        int row;
        if (m < (P_-1)*NSEL_) {
            int prel = m / NSEL_;
            int p    = prel + (prel >= i ? 1 : 0);
            int j    = m - prel * NSEL_;
            int tok  = is64 ? (int)i64[p*NSEL_ + j] : i32[p*NSEL_ + j];
            row = (s*P_ + p) * T_ + tok;
        } else {
            row = (s*P_ + i) * T_ + (m - (P_-1)*NSEL_);
        }
        g_kvrows[b*TK_ + m] = row;
    }
}

// ---------------------------------------------------------------------------
// 3xTF32 split-precision GEMM (unchanged from passing R4):
// Y[m][n] = sum_k A[m][k]*Bw[n][k] (+bias[n]); 128x128 tile, 8 warps.
// ---------------------------------------------------------------------------
__global__ __launch_bounds__(256) void gemm_mma_kernel(
    const float* __restrict__ A, const float* __restrict__ Bw,
    const float* __restrict__ bias, float* __restrict__ Y,
    int M, int N, int K)
{
    __shared__ float As[128][36];
    __shared__ float Bs[128][36];

    const int tid = threadIdx.x, wid = tid >> 5, lane = tid & 31;
    const int g = lane >> 2, tig = lane & 3;
    const int wm = (wid & 1) * 64, wn = (wid >> 1) * 32;
    const int m0 = blockIdx.y * 128, n0 = blockIdx.x * 128;
    const int NST = K >> 5;

    const int r = tid >> 1, half = tid & 1;
    const float* pA = A  + (size_t)(m0 + r) * K + half * 16;
    const float* pB = Bw + (size_t)(n0 + r) * K + half * 16;

    float acc[16][4];
    #pragma unroll
    for (int t = 0; t < 16; t++)
        #pragma unroll
        for (int v = 0; v < 4; v++) acc[t][v] = 0.f;

    float4 ra[4], rb[4];
    #pragma unroll
    for (int j = 0; j < 4; j++) {
        ra[j] = *(const float4*)(pA + j*4);
        rb[j] = *(const float4*)(pB + j*4);
    }

    for (int s = 0; s < NST; s++) {
        #pragma unroll
        for (int j = 0; j < 4; j++) {
            *(float4*)&As[r][half*16 + j*4] = ra[j];
            *(float4*)&Bs[r][half*16 + j*4] = rb[j];
        }
        __syncthreads();

        if (s + 1 < NST) {
            const float* a2 = pA + (s+1) * 32;
            const float* b2 = pB + (s+1) * 32;
            #pragma unroll
            for (int j = 0; j < 4; j++) {
                ra[j] = *(const float4*)(a2 + j*4);
                rb[j] = *(const float4*)(b2 + j*4);
            }
        }

        #pragma unroll
        for (int kb = 0; kb < 32; kb += 8) {
            uint32_t af[4][4], asm_[4][4], bf[4][2], bsm[4][2];
            #pragma unroll
            for (int mt = 0; mt < 4; mt++) {
                const int rb0 = wm + mt*16 + g;
                float v0 = As[rb0    ][kb + tig    ];
                float v1 = As[rb0 + 8][kb + tig    ];
                float v2 = As[rb0    ][kb + tig + 4];
                float v3 = As[rb0 + 8][kb + tig + 4];
                af[mt][0] = __float_as_uint(v0); asm_[mt][0] = tf32_small(v0);
                af[mt][1] = __float_as_uint(v1); asm_[mt][1] = tf32_small(v1);
                af[mt][2] = __float_as_uint(v2); asm_[mt][2] = tf32_small(v2);
                af[mt][3] = __float_as_uint(v3); asm_[mt][3] = tf32_small(v3);
            }
            #pragma unroll
            for (int nt = 0; nt < 4; nt++) {
                const int nb0 = wn + nt*8 + g;
                float w0 = Bs[nb0][kb + tig    ];
                float w1 = Bs[nb0][kb + tig + 4];
                bf[nt][0] = __float_as_uint(w0); bsm[nt][0] = tf32_small(w0);
                bf[nt][1] = __float_as_uint(w1); bsm[nt][1] = tf32_small(w1);
            }
            #pragma unroll
            for (int mt = 0; mt < 4; mt++)
                #pragma unroll
                for (int nt = 0; nt < 4; nt++) {
                    float* c = acc[mt*4 + nt];
                    mma_tf32(c, af[mt],   bf[nt]);
                    mma_tf32(c, af[mt],   bsm[nt]);
                    mma_tf32(c, asm_[mt], bf[nt]);
                }
        }
        __syncthreads();
    }

    #pragma unroll
    for (int mt = 0; mt < 4; mt++) {
        #pragma unroll
        for (int nt = 0; nt < 4; nt++) {
            const float* c = acc[mt*4 + nt];
            const int row = m0 + wm + mt*16 + g;
            const int col = n0 + wn + nt*8 + 2*tig;
            float b0c = 0.f, b1c = 0.f;
            if (bias) { b0c = bias[col]; b1c = bias[col + 1]; }
            float2 v0 = make_float2(c[0] + b0c, c[1] + b1c);
            float2 v1 = make_float2(c[2] + b0c, c[3] + b1c);
            *(float2*)(Y + (size_t)row       * N + col) = v0;
            *(float2*)(Y + (size_t)(row + 8) * N + col) = v1;
        }
    }
}

// ---------------------------------------------------------------------------
// Tensor-core flash attention (3xTF32 for S=Q@K^T and O+=P@V; fp32 softmax).
// Block = 64 q-rows x 1 head x 1 seq. 8 warps:
//   S phase:  warp(mt=w&3, nh=w>>2) owns S[mt*16..+16][nh*16..+16]
//   PV phase: warp(mt, nh) owns O[mt*16..+16][nh*32..+32]
// Q fragments (values) hoisted out of the chunk loop; smalls recomputed.
// Pads chosen conflict-free: Qs/Ks 68 (4g+tig), Vs 72 (8tig+g), Ss 36.
// ---------------------------------------------------------------------------
__global__ __launch_bounds__(256, 2) void attn_kernel() {
    __shared__ float Qs[BQ_][68];
    __shared__ float Ks[BKV_][68];
    __shared__ float Vs[BKV_][72];
    __shared__ float Ss[BQ_][36];
    __shared__ float rowscale[BQ_];
    __shared__ float rowinv[BQ_];

    const int qt = blockIdx.x, h = blockIdx.y, b = blockIdx.z;
    const int tid = threadIdx.x, wid = tid >> 5, lane = tid & 31;
    const int g = lane >> 2, tig = lane & 3;
    const int mt = wid & 3, nh = wid >> 2;     // S: nh in {0,1}; PV: nh*32 cols
    const int qm = mt * 16;
    const int rr = tid >> 2, qd = tid & 3;     // softmax mapping
    const int hoff = h * HD_;
    const int* rows = g_kvrows + b * TK_;

    // Load Q tile row-major, pre-scaled by 1/sqrt(hd)=0.125
    for (int idx = tid; idx < BQ_*HD_; idx += 256) {
        int r = idx >> 6, d = idx & 63;
        Qs[r][d] = g_Q[(size_t)(b*T_ + qt*BQ_ + r) * C_ + hoff + d] * 0.125f;
    }
    __syncthreads();

    // Hoist Q fragment VALUES (bits serve as tf32-big; smalls recomputed)
    float qv[8][4];
    #pragma unroll
    for (int ks = 0; ks < 8; ks++) {
        qv[ks][0] = Qs[qm + g    ][ks*8 + tig    ];
        qv[ks][1] = Qs[qm + g + 8][ks*8 + tig    ];
        qv[ks][2] = Qs[qm + g    ][ks*8 + tig + 4];
        qv[ks][3] = Qs[qm + g + 8][ks*8 + tig + 4];
    }

    float pacc[4][4];
    #pragma unroll
    for (int t = 0; t < 4; t++)
        #pragma unroll
        for (int v = 0; v < 4; v++) pacc[t][v] = 0.f;
    float m = -1e30f, l = 0.f;

    for (int ch = 0; ch < NCH_; ch++) {
        __syncthreads();   // prev PV reads of Ks/Vs/Ss done
        // Gather K/V chunk (row-major [j][d])
        for (int idx = tid; idx < BKV_*HD_; idx += 256) {
            int j = idx >> 6, d = idx & 63;
            int src = rows[ch*BKV_ + j];
            size_t gg = (size_t)src * C_ + hoff + d;
            Ks[j][d] = g_K[gg];
            Vs[j][d] = g_V[gg];
        }
        __syncthreads();

        // ---- S = Q @ K^T  (3xTF32) ----
        float sacc[2][4];
        #pragma unroll
        for (int nt = 0; nt < 2; nt++)
            #pragma unroll
            for (int v = 0; v < 4; v++) sacc[nt][v] = 0.f;
        #pragma unroll
        for (int ks = 0; ks < 8; ks++) {
            uint32_t qb[4], qs[4];
            #pragma unroll
            for (int i = 0; i < 4; i++) {
                qb[i] = __float_as_uint(qv[ks][i]);
                qs[i] = tf32_small(qv[ks][i]);
            }
            #pragma unroll
            for (int nt = 0; nt < 2; nt++) {
                const int jn = nh*16 + nt*8 + g;
                float w0 = Ks[jn][ks*8 + tig    ];
                float w1 = Ks[jn][ks*8 + tig + 4];
                uint32_t kb[2] = { __float_as_uint(w0), __float_as_uint(w1) };
                uint32_t ksm[2] = { tf32_small(w0), tf32_small(w1) };
                mma_tf32(sacc[nt], qb, kb);
                mma_tf32(sacc[nt], qb, ksm);
                mma_tf32(sacc[nt], qs, kb);
            }
        }
        #pragma unroll
        for (int nt = 0; nt < 2; nt++) {
            *(float2*)&Ss[qm + g    ][nh*16 + nt*8 + 2*tig] = make_float2(sacc[nt][0], sacc[nt][1]);
            *(float2*)&Ss[qm + g + 8][nh*16 + nt*8 + 2*tig] = make_float2(sacc[nt][2], sacc[nt][3]);
        }
        __syncthreads();

        // ---- online softmax (fp32, quad per row) ----
        float sv[8];
        #pragma unroll
        for (int w = 0; w < 8; w++) sv[w] = Ss[rr][qd*8 + w];
        float cm = sv[0];
        #pragma unroll
        for (int w = 1; w < 8; w++) cm = fmaxf(cm, sv[w]);
        cm = fmaxf(cm, __shfl_xor_sync(0xffffffffu, cm, 1));
        cm = fmaxf(cm, __shfl_xor_sync(0xffffffffu, cm, 2));
        float mn   = fmaxf(m, cm);
        float corr = __expf(m - mn);
        float ps   = 0.f;
        #pragma unroll
        for (int w = 0; w < 8; w++) {
            float p = __expf(sv[w] - mn);
            ps += p;
            Ss[rr][qd*8 + w] = p;
        }
        ps += __shfl_xor_sync(0xffffffffu, ps, 1);
        ps += __shfl_xor_sync(0xffffffffu, ps, 2);
        l = l * corr + ps;
        m = mn;
        if (qd == 0) rowscale[rr] = corr;
        __syncthreads();

        // ---- O = O*corr + P @ V  (3xTF32) ----
        const float s_g  = rowscale[qm + g];
        const float s_g8 = rowscale[qm + g + 8];
        #pragma unroll
        for (int nt = 0; nt < 4; nt++) {
            pacc[nt][0] *= s_g;  pacc[nt][1] *= s_g;
            pacc[nt][2] *= s_g8; pacc[nt][3] *= s_g8;
        }
        #pragma unroll
        for (int ks = 0; ks < 4; ks++) {
            float p0 = Ss[qm + g    ][ks*8 + tig    ];
            float p1 = Ss[qm + g + 8][ks*8 + tig    ];
            float p2 = Ss[qm + g    ][ks*8 + tig + 4];
            float p3 = Ss[qm + g + 8][ks*8 + tig + 4];
            uint32_t pb[4] = { __float_as_uint(p0), __float_as_uint(p1),
                               __float_as_uint(p2), __float_as_uint(p3) };
            uint32_t psm[4] = { tf32_small(p0), tf32_small(p1),
                                tf32_small(p2), tf32_small(p3) };
            #pragma unroll
            for (int nt = 0; nt < 4; nt++) {
                float w0 = Vs[ks*8 + tig    ][nh*32 + nt*8 + g];
                float w1 = Vs[ks*8 + tig + 4][nh*32 + nt*8 + g];
                uint32_t vb[2] = { __float_as_uint(w0), __float_as_uint(w1) };
                uint32_t vsm[2] = { tf32_small(w0), tf32_small(w1) };
                mma_tf32(pacc[nt], pb,  vb);
                mma_tf32(pacc[nt], pb,  vsm);
                mma_tf32(pacc[nt], psm, vb);
            }
        }
    }

    if (qd == 0) rowinv[rr] = 1.f / l;
    __syncthreads();

    const float i_g  = rowinv[qm + g];
    const float i_g8 = rowinv[qm + g + 8];
    const size_t orow0 = (size_t)(b*T_ + qt*BQ_ + qm + g) * C_ + hoff;
    #pragma unroll
    for (int nt = 0; nt < 4; nt++) {
        const int col = nh*32 + nt*8 + 2*tig;
        *(float2*)&g_AO[orow0 + col]          = make_float2(pacc[nt][0]*i_g,  pacc[nt][1]*i_g);
        *(float2*)&g_AO[orow0 + 8*C_ + col]   = make_float2(pacc[nt][2]*i_g8, pacc[nt][3]*i_g8);
    }
}

// ---------------------------------------------------------------------------
extern "C" void kernel_launch(void* const* d_in, const int* in_sizes, int n_in,
                              void* d_out, int out_size) {
    const float* hs  = (const float*)d_in[0];
    const float* Wq  = (const float*)d_in[1];
    const float* Wk  = (const float*)d_in[2];
    const float* Wv  = (const float*)d_in[3];
    const float* Wo  = (const float*)d_in[4];
    const float* bo  = (const float*)d_in[5];
    const void*  idx = d_in[6];
    float* out = (float*)d_out;

    float *Qp, *Kp, *Vp, *Ap;
    cudaGetSymbolAddress((void**)&Qp, g_Q);
    cudaGetSymbolAddress((void**)&Kp, g_K);
    cudaGetSymbolAddress((void**)&Vp, g_V);
    cudaGetSymbolAddress((void**)&Ap, g_AO);

    build_kv_kernel<<<B_, 256>>>(idx);

    dim3 gg(C_/128, (B_*T_)/128);       // (10, 45)
    gemm_mma_kernel<<<gg, 256>>>(hs, Wq, nullptr, Qp, B_*T_, C_, C_);
    gemm_mma_kernel<<<gg, 256>>>(hs, Wk, nullptr, Kp, B_*T_, C_, C_);
    gemm_mma_kernel<<<gg, 256>>>(hs, Wv, nullptr, Vp, B_*T_, C_, C_);

    dim3 ga(T_/BQ_, H_, B_);            // (9, 20, 10)
    attn_kernel<<<ga, 256>>>();

    gemm_mma_kernel<<<gg, 256>>>(Ap, Wo, bo, out, B_*T_, C_, C_);
}

// round 9
// speedup vs baseline: 1.7541x; 1.1287x over previous
#include <cuda_runtime.h>
#include <cstdint>

// Problem constants
#define B_    10      // 2 * IMG_COUNT sequences
#define T_    576     // tokens per sequence
#define C_    1280    // channels
#define H_    20      // heads
#define HD_   64      // head dim
#define P_    5       // plates
#define NSEL_ 288     // selected tokens per plate
#define TK_   1728    // kv length
#define BQ_   64
#define BKV_  32
#define NCH_  (TK_/BKV_)

// Scratch (device globals: allocation APIs are forbidden)
__device__ __align__(256) float g_Q [B_*T_*C_];
__device__ __align__(256) float g_K [B_*T_*C_];
__device__ __align__(256) float g_V [B_*T_*C_];
__device__ __align__(256) float g_AO[B_*T_*C_];
__device__ int g_kvrows[B_*TK_];

// ---------------------------------------------------------------------------
// Portable tf32 tensor-core MMA (sm_80+). HW reads operand bits[31:13] (RZ
// truncation) -- exploited for the big/small 3xTF32 split.
// ---------------------------------------------------------------------------
__device__ __forceinline__ void mma_tf32(float* c, const uint32_t* a, const uint32_t* b) {
    asm volatile(
        "mma.sync.aligned.m16n8k8.row.col.f32.tf32.tf32.f32 "
        "{%0,%1,%2,%3}, {%4,%5,%6,%7}, {%8,%9}, {%0,%1,%2,%3};"
        : "+f"(c[0]), "+f"(c[1]), "+f"(c[2]), "+f"(c[3])
        : "r"(a[0]), "r"(a[1]), "r"(a[2]), "r"(a[3]), "r"(b[0]), "r"(b[1]));
}

__device__ __forceinline__ uint32_t tf32_small(float v) {
    uint32_t big = __float_as_uint(v) & 0xFFFFE000u;
    return __float_as_uint(v - __uint_as_float(big));
}

__device__ __forceinline__ uint32_t smem_u32(const void* p) {
    uint32_t a;
    asm("{ .reg .u64 t; cvta.to.shared.u64 t, %1; cvt.u32.u64 %0, t; }" : "=r"(a) : "l"(p));
    return a;
}

#define CP_ASYNC16(smem, gptr) \
    asm volatile("cp.async.cg.shared.global [%0], [%1], 16;" :: "r"(smem), "l"(gptr))
#define CP_COMMIT()  asm volatile("cp.async.commit_group;" ::: "memory")
#define CP_WAIT(n)   asm volatile("cp.async.wait_group %0;" :: "n"(n) : "memory")

// ---------------------------------------------------------------------------
// Build per-(s,i) KV row index table (int64/int32 runtime detect).
// ---------------------------------------------------------------------------
__global__ void build_kv_kernel(const void* __restrict__ idx_raw) {
    const int*       i32 = (const int*)idx_raw;
    const long long* i64 = (const long long*)idx_raw;
    bool is64 = true;
    #pragma unroll 8
    for (int k = 0; k < 64; k++) {
        if (i32[2*k + 1] != 0) { is64 = false; break; }
    }
    const int b = blockIdx.x;
    const int s = b / P_, i = b % P_;
    for (int m = threadIdx.x; m < TK_; m += blockDim.x) {
        int row;
        if (m < (P_-1)*NSEL_) {
            int prel = m / NSEL_;
            int p    = prel + (prel >= i ? 1 : 0);
            int j    = m - prel * NSEL_;
            int tok  = is64 ? (int)i64[p*NSEL_ + j] : i32[p*NSEL_ + j];
            row = (s*P_ + p) * T_ + tok;
        } else {
            row = (s*P_ + i) * T_ + (m - (P_-1)*NSEL_);
        }
        g_kvrows[b*TK_ + m] = row;
    }
}

// ---------------------------------------------------------------------------
// 3xTF32 GEMM core (128x128 tile, 8 warps, BK=32). Shared by QKV and O.
// ---------------------------------------------------------------------------
__device__ __forceinline__ void gemm_tile_body(
    const float* __restrict__ A, const float* __restrict__ Bw,
    const float* __restrict__ bias, float* __restrict__ Y,
    int N, int K, int m0, int n0)
{
    __shared__ float As[128][36];
    __shared__ float Bs[128][36];

    const int tid = threadIdx.x, wid = tid >> 5, lane = tid & 31;
    const int g = lane >> 2, tig = lane & 3;
    const int wm = (wid & 1) * 64, wn = (wid >> 1) * 32;
    const int NST = K >> 5;

    const int r = tid >> 1, half = tid & 1;
    const float* pA = A  + (size_t)(m0 + r) * K + half * 16;
    const float* pB = Bw + (size_t)(n0 + r) * K + half * 16;

    float acc[16][4];
    #pragma unroll
    for (int t = 0; t < 16; t++)
        #pragma unroll
        for (int v = 0; v < 4; v++) acc[t][v] = 0.f;

    float4 ra[4], rb[4];
    #pragma unroll
    for (int j = 0; j < 4; j++) {
        ra[j] = *(const float4*)(pA + j*4);
        rb[j] = *(const float4*)(pB + j*4);
    }

    for (int s = 0; s < NST; s++) {
        #pragma unroll
        for (int j = 0; j < 4; j++) {
            *(float4*)&As[r][half*16 + j*4] = ra[j];
            *(float4*)&Bs[r][half*16 + j*4] = rb[j];
        }
        __syncthreads();

        if (s + 1 < NST) {
            const float* a2 = pA + (s+1) * 32;
            const float* b2 = pB + (s+1) * 32;
            #pragma unroll
            for (int j = 0; j < 4; j++) {
                ra[j] = *(const float4*)(a2 + j*4);
                rb[j] = *(const float4*)(b2 + j*4);
            }
        }

        #pragma unroll
        for (int kb = 0; kb < 32; kb += 8) {
            uint32_t af[4][4], asm_[4][4], bf[4][2], bsm[4][2];
            #pragma unroll
            for (int mt = 0; mt < 4; mt++) {
                const int rb0 = wm + mt*16 + g;
                float v0 = As[rb0    ][kb + tig    ];
                float v1 = As[rb0 + 8][kb + tig    ];
                float v2 = As[rb0    ][kb + tig + 4];
                float v3 = As[rb0 + 8][kb + tig + 4];
                af[mt][0] = __float_as_uint(v0); asm_[mt][0] = tf32_small(v0);
                af[mt][1] = __float_as_uint(v1); asm_[mt][1] = tf32_small(v1);
                af[mt][2] = __float_as_uint(v2); asm_[mt][2] = tf32_small(v2);
                af[mt][3] = __float_as_uint(v3); asm_[mt][3] = tf32_small(v3);
            }
            #pragma unroll
            for (int nt = 0; nt < 4; nt++) {
                const int nb0 = wn + nt*8 + g;
                float w0 = Bs[nb0][kb + tig    ];
                float w1 = Bs[nb0][kb + tig + 4];
                bf[nt][0] = __float_as_uint(w0); bsm[nt][0] = tf32_small(w0);
                bf[nt][1] = __float_as_uint(w1); bsm[nt][1] = tf32_small(w1);
            }
            #pragma unroll
            for (int mt = 0; mt < 4; mt++)
                #pragma unroll
                for (int nt = 0; nt < 4; nt++) {
                    float* c = acc[mt*4 + nt];
                    mma_tf32(c, af[mt],   bf[nt]);
                    mma_tf32(c, af[mt],   bsm[nt]);
                    mma_tf32(c, asm_[mt], bf[nt]);
                }
        }
        __syncthreads();
    }

    #pragma unroll
    for (int mt = 0; mt < 4; mt++) {
        #pragma unroll
        for (int nt = 0; nt < 4; nt++) {
            const float* c = acc[mt*4 + nt];
            const int row = m0 + wm + mt*16 + g;
            const int col = n0 + wn + nt*8 + 2*tig;
            float b0c = 0.f, b1c = 0.f;
            if (bias) { b0c = bias[col]; b1c = bias[col + 1]; }
            float2 v0 = make_float2(c[0] + b0c, c[1] + b1c);
            float2 v1 = make_float2(c[2] + b0c, c[3] + b1c);
            *(float2*)(Y + (size_t)row       * N + col) = v0;
            *(float2*)(Y + (size_t)(row + 8) * N + col) = v1;
        }
    }
}

// Fused Q/K/V projection: blockIdx.z selects weight + destination.
__global__ __launch_bounds__(256) void gemm_qkv_kernel(
    const float* __restrict__ hs,
    const float* __restrict__ Wq, const float* __restrict__ Wk,
    const float* __restrict__ Wv,
    float* __restrict__ Qp, float* __restrict__ Kp, float* __restrict__ Vp)
{
    const int z = blockIdx.z;
    const float* Bw = (z == 0) ? Wq : (z == 1) ? Wk : Wv;
    float*       Y  = (z == 0) ? Qp : (z == 1) ? Kp : Vp;
    gemm_tile_body(hs, Bw, nullptr, Y, C_, C_, blockIdx.y * 128, blockIdx.x * 128);
}

// Output projection (with bias).
__global__ __launch_bounds__(256) void gemm_o_kernel(
    const float* __restrict__ A, const float* __restrict__ Wo,
    const float* __restrict__ bo, float* __restrict__ Y)
{
    gemm_tile_body(A, Wo, bo, Y, C_, C_, blockIdx.y * 128, blockIdx.x * 128);
}

// ---------------------------------------------------------------------------
// Tensor-core flash attention (3xTF32), cp.async double-buffered K/V gather.
// Dynamic smem layout (floats):
//   Qs[64][68] | Ks[2][32][68] | Vs[2][32][72] | Ss[64][36]
//   | rowscale[64] | rowinv[64] | rows_s[1728 ints]
// ---------------------------------------------------------------------------
#define QS_OFF   0
#define KS_OFF   (QS_OFF + BQ_*68)            // 4352
#define VS_OFF   (KS_OFF + 2*BKV_*68)          // 8704
#define SS_OFF   (VS_OFF + 2*BKV_*72)          // 13312
#define RSC_OFF  (SS_OFF + BQ_*36)             // 15616
#define RIV_OFF  (RSC_OFF + BQ_)
#define ROWS_OFF (RIV_OFF + BQ_)
#define ATTN_SMEM_FLOATS (ROWS_OFF + TK_)      // 19472 floats = 77888 B
#define ATTN_SMEM_BYTES  (ATTN_SMEM_FLOATS * 4)

__global__ __launch_bounds__(256, 2) void attn_kernel() {
    extern __shared__ float smx[];
    float (*Qs)[68] = (float(*)[68])(smx + QS_OFF);
    float (*Ks)[68] = (float(*)[68])(smx + KS_OFF);   // [2*32][68]
    float (*Vs)[72] = (float(*)[72])(smx + VS_OFF);   // [2*32][72]
    float (*Ss)[36] = (float(*)[36])(smx + SS_OFF);
    float* rowscale = smx + RSC_OFF;
    float* rowinv   = smx + RIV_OFF;
    int*   rows_s   = (int*)(smx + ROWS_OFF);

    const uint32_t ks_base = smem_u32(&Ks[0][0]);
    const uint32_t vs_base = smem_u32(&Vs[0][0]);

    const int qt = blockIdx.x, h = blockIdx.y, b = blockIdx.z;
    const int tid = threadIdx.x, wid = tid >> 5, lane = tid & 31;
    const int g = lane >> 2, tig = lane & 3;
    const int mt = wid & 3, nh = wid >> 2;
    const int qm = mt * 16;
    const int rr = tid >> 2, qd = tid & 3;
    const int hoff = h * HD_;

    // Stage row indices + Q tile
    for (int m = tid; m < TK_; m += 256) rows_s[m] = g_kvrows[b*TK_ + m];
    for (int idx = tid; idx < BQ_*HD_; idx += 256) {
        int r = idx >> 6, d = idx & 63;
        Qs[r][d] = g_Q[(size_t)(b*T_ + qt*BQ_ + r) * C_ + hoff + d] * 0.125f;
    }
    __syncthreads();

    // cp.async gather of one chunk into buffer `buf`
    const int pj = tid >> 4, pd = (tid & 15) << 2;   // t=0 mapping; t=1 adds 16 rows
    auto prefetch = [&](int ch, int buf) {
        #pragma unroll
        for (int t = 0; t < 2; t++) {
            int j = pj + t*16;
            int src = rows_s[ch*BKV_ + j];
            const float* gk = g_K + (size_t)src * C_ + hoff + pd;
            const float* gv = g_V + (size_t)src * C_ + hoff + pd;
            uint32_t sk = ks_base + (uint32_t)(((buf*BKV_ + j)*68 + pd) * 4);
            uint32_t sv = vs_base + (uint32_t)(((buf*BKV_ + j)*72 + pd) * 4);
            CP_ASYNC16(sk, gk);
            CP_ASYNC16(sv, gv);
        }
        CP_COMMIT();
    };

    prefetch(0, 0);

    // Hoist Q fragment VALUES
    float qv[8][4];
    #pragma unroll
    for (int ks = 0; ks < 8; ks++) {
        qv[ks][0] = Qs[qm + g    ][ks*8 + tig    ];
        qv[ks][1] = Qs[qm + g + 8][ks*8 + tig    ];
        qv[ks][2] = Qs[qm + g    ][ks*8 + tig + 4];
        qv[ks][3] = Qs[qm + g + 8][ks*8 + tig + 4];
    }

    float pacc[4][4];
    #pragma unroll
    for (int t = 0; t < 4; t++)
        #pragma unroll
        for (int v = 0; v < 4; v++) pacc[t][v] = 0.f;
    float m = -1e30f, l = 0.f;

    for (int ch = 0; ch < NCH_; ch++) {
        const int cur = ch & 1;
        __syncthreads();                    // prior PV reads of buf 1-cur done
        if (ch + 1 < NCH_) { prefetch(ch + 1, 1 - cur); CP_WAIT(1); }
        else               { CP_WAIT(0); }
        __syncthreads();                    // cur buffer visible to all

        const float (*Kc)[68] = Ks + cur*BKV_;
        const float (*Vc)[72] = Vs + cur*BKV_;

        // ---- S = Q @ K^T  (3xTF32) ----
        float sacc[2][4];
        #pragma unroll
        for (int nt = 0; nt < 2; nt++)
            #pragma unroll
            for (int v = 0; v < 4; v++) sacc[nt][v] = 0.f;
        #pragma unroll
        for (int ks = 0; ks < 8; ks++) {
            uint32_t qb[4], qs[4];
            #pragma unroll
            for (int i = 0; i < 4; i++) {
                qb[i] = __float_as_uint(qv[ks][i]);
                qs[i] = tf32_small(qv[ks][i]);
            }
            #pragma unroll
            for (int nt = 0; nt < 2; nt++) {
                const int jn = nh*16 + nt*8 + g;
                float w0 = Kc[jn][ks*8 + tig    ];
                float w1 = Kc[jn][ks*8 + tig + 4];
                uint32_t kb[2] = { __float_as_uint(w0), __float_as_uint(w1) };
                uint32_t ksm[2] = { tf32_small(w0), tf32_small(w1) };
                mma_tf32(sacc[nt], qb, kb);
                mma_tf32(sacc[nt], qb, ksm);
                mma_tf32(sacc[nt], qs, kb);
            }
        }
        #pragma unroll
        for (int nt = 0; nt < 2; nt++) {
            *(float2*)&Ss[qm + g    ][nh*16 + nt*8 + 2*tig] = make_float2(sacc[nt][0], sacc[nt][1]);
            *(float2*)&Ss[qm + g + 8][nh*16 + nt*8 + 2*tig] = make_float2(sacc[nt][2], sacc[nt][3]);
        }
        __syncthreads();

        // ---- online softmax (fp32, quad per row) ----
        float sv[8];
        #pragma unroll
        for (int w = 0; w < 8; w++) sv[w] = Ss[rr][qd*8 + w];
        float cm = sv[0];
        #pragma unroll
        for (int w = 1; w < 8; w++) cm = fmaxf(cm, sv[w]);
        cm = fmaxf(cm, __shfl_xor_sync(0xffffffffu, cm, 1));
        cm = fmaxf(cm, __shfl_xor_sync(0xffffffffu, cm, 2));
        float mn   = fmaxf(m, cm);
        float corr = __expf(m - mn);
        float ps   = 0.f;
        #pragma unroll
        for (int w = 0; w < 8; w++) {
            float p = __expf(sv[w] - mn);
            ps += p;
            Ss[rr][qd*8 + w] = p;
        }
        ps += __shfl_xor_sync(0xffffffffu, ps, 1);
        ps += __shfl_xor_sync(0xffffffffu, ps, 2);
        l = l * corr + ps;
        m = mn;
        if (qd == 0) rowscale[rr] = corr;
        __syncthreads();

        // ---- O = O*corr + P @ V  (3xTF32) ----
        const float s_g  = rowscale[qm + g];
        const float s_g8 = rowscale[qm + g + 8];
        #pragma unroll
        for (int nt = 0; nt < 4; nt++) {
            pacc[nt][0] *= s_g;  pacc[nt][1] *= s_g;
            pacc[nt][2] *= s_g8; pacc[nt][3] *= s_g8;
        }
        #pragma unroll
        for (int ks = 0; ks < 4; ks++) {
            float p0 = Ss[qm + g    ][ks*8 + tig    ];
            float p1 = Ss[qm + g + 8][ks*8 + tig    ];
            float p2 = Ss[qm + g    ][ks*8 + tig + 4];
            float p3 = Ss[qm + g + 8][ks*8 + tig + 4];
            uint32_t pb[4] = { __float_as_uint(p0), __float_as_uint(p1),
                               __float_as_uint(p2), __float_as_uint(p3) };
            uint32_t psm[4] = { tf32_small(p0), tf32_small(p1),
                                tf32_small(p2), tf32_small(p3) };
            #pragma unroll
            for (int nt = 0; nt < 4; nt++) {
                float w0 = Vc[ks*8 + tig    ][nh*32 + nt*8 + g];
                float w1 = Vc[ks*8 + tig + 4][nh*32 + nt*8 + g];
                uint32_t vb[2] = { __float_as_uint(w0), __float_as_uint(w1) };
                uint32_t vsm[2] = { tf32_small(w0), tf32_small(w1) };
                mma_tf32(pacc[nt], pb,  vb);
                mma_tf32(pacc[nt], pb,  vsm);
                mma_tf32(pacc[nt], psm, vb);
            }
        }
    }

    if (qd == 0) rowinv[rr] = 1.f / l;
    __syncthreads();

    const float i_g  = rowinv[qm + g];
    const float i_g8 = rowinv[qm + g + 8];
    const size_t orow0 = (size_t)(b*T_ + qt*BQ_ + qm + g) * C_ + hoff;
    #pragma unroll
    for (int nt = 0; nt < 4; nt++) {
        const int col = nh*32 + nt*8 + 2*tig;
        *(float2*)&g_AO[orow0 + col]          = make_float2(pacc[nt][0]*i_g,  pacc[nt][1]*i_g);
        *(float2*)&g_AO[orow0 + 8*C_ + col]   = make_float2(pacc[nt][2]*i_g8, pacc[nt][3]*i_g8);
    }
}

// ---------------------------------------------------------------------------
extern "C" void kernel_launch(void* const* d_in, const int* in_sizes, int n_in,
                              void* d_out, int out_size) {
    const float* hs  = (const float*)d_in[0];
    const float* Wq  = (const float*)d_in[1];
    const float* Wk  = (const float*)d_in[2];
    const float* Wv  = (const float*)d_in[3];
    const float* Wo  = (const float*)d_in[4];
    const float* bo  = (const float*)d_in[5];
    const void*  idx = d_in[6];
    float* out = (float*)d_out;

    float *Qp, *Kp, *Vp, *Ap;
    cudaGetSymbolAddress((void**)&Qp, g_Q);
    cudaGetSymbolAddress((void**)&Kp, g_K);
    cudaGetSymbolAddress((void**)&Vp, g_V);
    cudaGetSymbolAddress((void**)&Ap, g_AO);

    // Host-side attribute set; idempotent, called unconditionally (no static
    // guards per harness contract).
    cudaFuncSetAttribute(attn_kernel,
                         cudaFuncAttributeMaxDynamicSharedMemorySize,
                         ATTN_SMEM_BYTES);

    build_kv_kernel<<<B_, 256>>>(idx);

    dim3 gq(C_/128, (B_*T_)/128, 3);    // (10, 45, 3) = 1350 CTAs, one wave set
    gemm_qkv_kernel<<<gq, 256>>>(hs, Wq, Wk, Wv, Qp, Kp, Vp);

    dim3 ga(T_/BQ_, H_, B_);            // (9, 20, 10)
    attn_kernel<<<ga, 256, ATTN_SMEM_BYTES>>>();

    dim3 gg(C_/128, (B_*T_)/128);       // (10, 45)
    gemm_o_kernel<<<gg, 256>>>(Ap, Wo, bo, out);
}